// round 10
// baseline (speedup 1.0000x reference)
#include <cuda_runtime.h>
#include <cuda_bf16.h>
#include <cstdint>

#define NN     50000
#define EE     800000
#define EI     200000
#define SLOPE  0.2f

// ---- scratch layout inside d_out (float offsets) -------------------------------
// d_out = NN*128 + EI*256 = 57,600,000 floats. h lives at [0, 6.4M).
// The edges region [6.4M, 57.6M) is written only by the LAST kernel; its front
// is scratch for everything else:
#define S_FT    6400000u     // 6.4M floats : projected features (per layer)
#define S_H1   12800000u     // 6.4M floats : layer-1 output
#define S_EL   19200000u     // 0.2M
#define S_ER   19400000u     // 0.2M
#define S_OFF  19600000u     // NN+1 ints : CSR row offsets
#define S_CUR  19800000u     // NN   ints : counts -> cursors
#define S_EIDX 20000000u     // EE   ints : src id per CSR slot
#define S_DST  20800000u     // EE   ints : dst id per CSR slot
#define S_A    21600000u     // EE*4 floats : attention per slot (ends 24.8M < 57.6M)

// ---------------- packed f32x2 helpers (Blackwell FFMA2) ------------------------
__device__ __forceinline__ unsigned long long pk2(float lo, float hi) {
    unsigned long long r;
    asm("mov.b64 %0, {%1, %2};" : "=l"(r) : "f"(lo), "f"(hi));
    return r;
}
__device__ __forceinline__ void ffma2(unsigned long long& d,
                                      unsigned long long a, unsigned long long b) {
    asm("fma.rn.f32x2 %0, %1, %2, %0;" : "+l"(d) : "l"(a), "l"(b));
}
__device__ __forceinline__ float2 up2(unsigned long long v) {
    float2 f;
    asm("mov.b64 {%0, %1}, %2;" : "=f"(f.x), "=f"(f.y) : "l"(v));
    return f;
}

// =================================================================================
// GEMM (measured 57.3us): ft = X @ W, fused el/er.
// 512 threads, 128-row tile, micro-tile 8x4 per thread, packed FFMA2.
// =================================================================================
#define XPAD 132
__global__ void __launch_bounds__(512, 1)
gat_gemm_kernel(const float* __restrict__ X, const float* __restrict__ W,
                const float* __restrict__ al, const float* __restrict__ ar,
                float* __restrict__ ft, float* __restrict__ el,
                float* __restrict__ er)
{
    extern __shared__ float smem[];
    float* Ws = smem;             // [128][128]
    float* Xs = smem + 16384;     // [128][XPAD]  Xs[k*XPAD + r]

    const int t    = threadIdx.x;
    const int lane = t & 31;
    const int warp = t >> 5;      // 0..15
    const int c0   = lane * 4;
    const int r0   = warp * 8;
    const int row0 = blockIdx.x * 128;

    {
        const float4* W4 = reinterpret_cast<const float4*>(W);
        float4* Ws4 = reinterpret_cast<float4*>(Ws);
        #pragma unroll
        for (int i = t; i < 4096; i += 512) Ws4[i] = W4[i];
    }
    const float4 alv = reinterpret_cast<const float4*>(al)[lane];
    const float4 arv = reinterpret_cast<const float4*>(ar)[lane];

    for (int i = t; i < 128 * 128; i += 512) {
        int r = i >> 7, k = i & 127;
        int row = row0 + r;
        Xs[k * XPAD + r] = (row < NN) ? X[(size_t)row * 128 + k] : 0.f;
    }
    __syncthreads();

    unsigned long long acc[4][4];
    #pragma unroll
    for (int rp = 0; rp < 4; rp++)
        #pragma unroll
        for (int c = 0; c < 4; c++) acc[rp][c] = 0ull;

    #pragma unroll 4
    for (int k = 0; k < 128; k++) {
        float4 w  = *reinterpret_cast<const float4*>(&Ws[k * 128 + c0]);
        float4 x0 = *reinterpret_cast<const float4*>(&Xs[k * XPAD + r0]);
        float4 x1 = *reinterpret_cast<const float4*>(&Xs[k * XPAD + r0 + 4]);
        unsigned long long ww[4] = {pk2(w.x, w.x), pk2(w.y, w.y),
                                    pk2(w.z, w.z), pk2(w.w, w.w)};
        unsigned long long xp[4] = {pk2(x0.x, x0.y), pk2(x0.z, x0.w),
                                    pk2(x1.x, x1.y), pk2(x1.z, x1.w)};
        #pragma unroll
        for (int rp = 0; rp < 4; rp++) {
            ffma2(acc[rp][0], xp[rp], ww[0]);
            ffma2(acc[rp][1], xp[rp], ww[1]);
            ffma2(acc[rp][2], xp[rp], ww[2]);
            ffma2(acc[rp][3], xp[rp], ww[3]);
        }
    }

    #pragma unroll
    for (int r = 0; r < 8; r++) {
        int rp = r >> 1, hl = r & 1;
        float v0 = hl ? up2(acc[rp][0]).y : up2(acc[rp][0]).x;
        float v1 = hl ? up2(acc[rp][1]).y : up2(acc[rp][1]).x;
        float v2 = hl ? up2(acc[rp][2]).y : up2(acc[rp][2]).x;
        float v3 = hl ? up2(acc[rp][3]).y : up2(acc[rp][3]).x;
        int row = row0 + r0 + r;
        float pe = v0*alv.x + v1*alv.y + v2*alv.z + v3*alv.w;
        float pr = v0*arv.x + v1*arv.y + v2*arv.z + v3*arv.w;
        pe += __shfl_down_sync(0xffffffffu, pe, 4, 8);
        pe += __shfl_down_sync(0xffffffffu, pe, 2, 8);
        pe += __shfl_down_sync(0xffffffffu, pe, 1, 8);
        pr += __shfl_down_sync(0xffffffffu, pr, 4, 8);
        pr += __shfl_down_sync(0xffffffffu, pr, 2, 8);
        pr += __shfl_down_sync(0xffffffffu, pr, 1, 8);
        if (row < NN) {
            *reinterpret_cast<float4*>(&ft[(size_t)row * 128 + c0]) =
                make_float4(v0, v1, v2, v3);
            if ((lane & 7) == 0) {
                int h = lane >> 3;
                el[(size_t)row * 4 + h] = pe;
                er[(size_t)row * 4 + h] = pr;
            }
        }
    }
}

// =================================================================================
// CSR build (once per call; graph reused by both layers)
// =================================================================================
__global__ void hist_kernel(const int* __restrict__ dst, int* __restrict__ cnt)
{
    int e = blockIdx.x * blockDim.x + threadIdx.x;
    if (e < EE) atomicAdd(&cnt[dst[e]], 1);
}

__global__ void __launch_bounds__(1024, 1)
scan_kernel(int* __restrict__ cntcur, int* __restrict__ off)
{
    __shared__ int ssum[1024];
    const int t = threadIdx.x;
    const int C = (NN + 1023) / 1024;
    int lo = t * C, hi = min(lo + C, NN);
    int s = 0;
    for (int i = lo; i < hi; i++) s += cntcur[i];
    ssum[t] = s;
    __syncthreads();
    for (int d = 1; d < 1024; d <<= 1) {
        int v = (t >= d) ? ssum[t - d] : 0;
        __syncthreads();
        ssum[t] += v;
        __syncthreads();
    }
    int run = (t > 0) ? ssum[t - 1] : 0;
    for (int i = lo; i < hi; i++) {
        int c = cntcur[i];
        off[i] = run;
        cntcur[i] = run;        // becomes scatter cursor
        run += c;
    }
    if (t == 1023) off[NN] = ssum[1023];
}

__global__ void scatter_kernel(const int* __restrict__ src, const int* __restrict__ dst,
                               int* __restrict__ cur, int* __restrict__ eidx,
                               int* __restrict__ dslot)
{
    int e = blockIdx.x * blockDim.x + threadIdx.x;
    if (e >= EE) return;
    int d = dst[e];
    int pos = atomicAdd(&cur[d], 1);
    eidx[pos]  = src[e];
    dslot[pos] = d;
}

// =================================================================================
// Edge-parallel attention precompute (streaming): a4[slot] = exp(leaky(el[s]+er[d]))
// =================================================================================
__global__ void att_kernel(const int* __restrict__ eidx, const int* __restrict__ dslot,
                           const float* __restrict__ el, const float* __restrict__ er,
                           float4* __restrict__ a4)
{
    int t = blockIdx.x * blockDim.x + threadIdx.x;
    if (t >= EE) return;
    int s = eidx[t], d = dslot[t];
    float4 l = *reinterpret_cast<const float4*>(&el[(size_t)s * 4]);
    float4 r = *reinterpret_cast<const float4*>(&er[(size_t)d * 4]);
    float4 v;
    float vx = l.x + r.x; vx = (vx > 0.f) ? vx : SLOPE * vx; v.x = __expf(vx);
    float vy = l.y + r.y; vy = (vy > 0.f) ? vy : SLOPE * vy; v.y = __expf(vy);
    float vz = l.z + r.z; vz = (vz > 0.f) ? vz : SLOPE * vz; v.z = __expf(vz);
    float vw = l.w + r.w; vw = (vw > 0.f) ? vw : SLOPE * vw; v.w = __expf(vw);
    a4[t] = v;
}

// =================================================================================
// Gather aggregation + fused normalize + ELU. One warp per dst node.
// Attention pre-computed; loop = prefetched int4 src ids + coalesced a block +
// 4 ft gathers. launch_bounds(256,4) -> 64-reg budget, no spills.
// =================================================================================
__device__ __forceinline__ float elu1(float x) { return (x > 0.f) ? x : expm1f(x); }

__global__ void __launch_bounds__(256, 4)
gat_aggregate_kernel(const int* __restrict__ off, const int* __restrict__ eidx,
                     const float* __restrict__ afl, const float* __restrict__ ft,
                     float* __restrict__ out)
{
    int d = (blockIdx.x * blockDim.x + threadIdx.x) >> 5;
    if (d >= NN) return;
    const int lane = threadIdx.x & 31;
    const int hsel = lane >> 3;            // head of this lane's float4 chunk

    int p0 = off[d], p1 = off[d + 1];
    float4 acc = make_float4(0.f, 0.f, 0.f, 0.f);
    float den16 = 0.f;                     // lanes 0..15 partial denom, head lane&3
    const float4* ft4 = reinterpret_cast<const float4*>(ft);

    int p = p0;
    // head singles until 16B-aligned
    int pre = min(p1, (p0 + 3) & ~3);
    for (; p < pre; ++p) {
        int s = __ldg(&eidx[p]);
        float4 f = ft4[(size_t)s * 32 + lane];
        float a = (lane < 4) ? __ldg(&afl[(size_t)p * 4 + lane]) : 0.f;
        if (lane < 4) den16 += a;
        float ah = __shfl_sync(0xffffffffu, a, hsel);
        acc.x += ah * f.x; acc.y += ah * f.y;
        acc.z += ah * f.z; acc.w += ah * f.w;
    }
    // aligned 4-edge blocks with src-id prefetch
    if (p + 4 <= p1) {
        int4 s4 = __ldg(reinterpret_cast<const int4*>(&eidx[p]));
        for (; p + 4 <= p1; p += 4) {
            int4 nxt = (p + 8 <= p1)
                     ? __ldg(reinterpret_cast<const int4*>(&eidx[p + 4])) : s4;
            float a = 0.f;
            if (lane < 16) {               // lane = e*4 + h, coalesced 64B
                a = __ldg(&afl[(size_t)p * 4 + lane]);
                den16 += a;
            }
            float4 f0 = ft4[(size_t)s4.x * 32 + lane];
            float4 f1 = ft4[(size_t)s4.y * 32 + lane];
            float4 f2 = ft4[(size_t)s4.z * 32 + lane];
            float4 f3 = ft4[(size_t)s4.w * 32 + lane];
            float h0 = __shfl_sync(0xffffffffu, a, hsel);
            float h1 = __shfl_sync(0xffffffffu, a, 4 + hsel);
            float h2 = __shfl_sync(0xffffffffu, a, 8 + hsel);
            float h3 = __shfl_sync(0xffffffffu, a, 12 + hsel);
            acc.x += h0 * f0.x + h1 * f1.x + h2 * f2.x + h3 * f3.x;
            acc.y += h0 * f0.y + h1 * f1.y + h2 * f2.y + h3 * f3.y;
            acc.z += h0 * f0.z + h1 * f1.z + h2 * f2.z + h3 * f3.z;
            acc.w += h0 * f0.w + h1 * f1.w + h2 * f2.w + h3 * f3.w;
            s4 = nxt;
        }
    }
    // tail singles
    for (; p < p1; ++p) {
        int s = __ldg(&eidx[p]);
        float4 f = ft4[(size_t)s * 32 + lane];
        float a = (lane < 4) ? __ldg(&afl[(size_t)p * 4 + lane]) : 0.f;
        if (lane < 4) den16 += a;
        float ah = __shfl_sync(0xffffffffu, a, hsel);
        acc.x += ah * f.x; acc.y += ah * f.y;
        acc.z += ah * f.z; acc.w += ah * f.w;
    }

    // reduce den over lane groups: lanes 0..3 end with den[h]
    den16 += __shfl_down_sync(0xffffffffu, den16, 8);
    den16 += __shfl_down_sync(0xffffffffu, den16, 4);
    float inv  = 1.0f / fmaxf(den16, 1e-9f);
    float invh = __shfl_sync(0xffffffffu, inv, hsel);
    float4 r;
    r.x = elu1(acc.x * invh);
    r.y = elu1(acc.y * invh);
    r.z = elu1(acc.z * invh);
    r.w = elu1(acc.w * invh);
    reinterpret_cast<float4*>(out)[(size_t)d * 32 + lane] = r;
}

// =================================================================================
// Edge features: out[p, h*64 + 0..31] = hf[i0,h,:], [32..63] = hf[i1,h,:]
// =================================================================================
__global__ void gat_edgefeat_kernel(const float* __restrict__ hf,
                                    const int* __restrict__ ind0,
                                    const int* __restrict__ ind1,
                                    float* __restrict__ out)
{
    int idx = blockIdx.x * blockDim.x + threadIdx.x;
    if (idx >= EI * 64) return;
    int p = idx >> 6;
    int q = idx & 63;
    int h = q >> 4;
    int w = q & 15;
    int node = (w < 8) ? __ldg(&ind0[p]) : __ldg(&ind1[p]);
    float4 v = reinterpret_cast<const float4*>(hf)[(size_t)node * 32 + h * 8 + (w & 7)];
    reinterpret_cast<float4*>(out)[(size_t)p * 64 + q] = v;
}

// =================================================================================
// Launch
// =================================================================================
extern "C" void kernel_launch(void* const* d_in, const int* in_sizes, int n_in,
                              void* d_out, int out_size)
{
    const float* x      = (const float*)d_in[0];
    const int*   src    = (const int*)  d_in[1];
    const int*   dst    = (const int*)  d_in[2];
    const int*   indics = (const int*)  d_in[3];
    const float* W0     = (const float*)d_in[4];
    const float* al0    = (const float*)d_in[5];
    const float* ar0    = (const float*)d_in[6];
    const float* W1     = (const float*)d_in[7];
    const float* al1    = (const float*)d_in[8];
    const float* ar1    = (const float*)d_in[9];

    float* o     = (float*)d_out;
    float* h_out = o;                      // [N, 128]
    float* edges = o + (size_t)NN * 128;   // [E_IND, 256] (written LAST)

    float* ft   = o + S_FT;
    float* h1   = o + S_H1;
    float* el   = o + S_EL;
    float* er   = o + S_ER;
    int*   off  = (int*)(o + S_OFF);
    int*   cur  = (int*)(o + S_CUR);
    int*   eid  = (int*)(o + S_EIDX);
    int*   dsl  = (int*)(o + S_DST);
    float* afl  = o + S_A;
    float4* a4  = (float4*)afl;

    const int gemm_smem = (16384 + 128 * XPAD) * 4;    // 133,120 B
    static int attr_done = 0;
    if (!attr_done) {
        cudaFuncSetAttribute(gat_gemm_kernel,
                             cudaFuncAttributeMaxDynamicSharedMemorySize, gemm_smem);
        attr_done = 1;
    }

    const int gemm_grid = (NN + 127) / 128;            // 391
    const int edge_grid = (EE + 255) / 256;
    const int agg_grid  = (NN * 32 + 255) / 256;
    const int ef_grid   = (EI * 64 + 255) / 256;

    // ---- CSR build ----
    cudaMemsetAsync(cur, 0, NN * sizeof(int));
    hist_kernel<<<edge_grid, 256>>>(dst, cur);
    scan_kernel<<<1, 1024>>>(cur, off);
    scatter_kernel<<<edge_grid, 256>>>(src, dst, cur, eid, dsl);

    // ---- layer 1 ----
    gat_gemm_kernel<<<gemm_grid, 512, gemm_smem>>>(x, W0, al0, ar0, ft, el, er);
    att_kernel<<<edge_grid, 256>>>(eid, dsl, el, er, a4);
    gat_aggregate_kernel<<<agg_grid, 256>>>(off, eid, afl, ft, h1);   // <- ncu captures this

    // ---- layer 2 ----
    gat_gemm_kernel<<<gemm_grid, 512, gemm_smem>>>(h1, W1, al1, ar1, ft, el, er);
    att_kernel<<<edge_grid, 256>>>(eid, dsl, el, er, a4);
    gat_aggregate_kernel<<<agg_grid, 256>>>(off, eid, afl, ft, h_out);

    // ---- edge features (overwrites scratch region last) ----
    gat_edgefeat_kernel<<<ef_grid, 256>>>(h_out, indics, indics + EI, edges);
}

// round 12
// speedup vs baseline: 1.0206x; 1.0206x over previous
#include <cuda_runtime.h>
#include <cuda_fp16.h>
#include <cstdint>

#define NN     50000
#define EE     800000
#define EI     200000
#define SLOPE  0.2f

// ---- scratch layout inside d_out (float offsets) -------------------------------
// d_out = NN*128 + EI*256 = 57,600,000 floats. h lives at [0, 6.4M).
// The edges region [6.4M, 57.6M) is written only by the LAST kernel; its front
// is scratch for everything else:
#define S_FT    6400000u     // 3.2M floats used: NN*128 halves (fp16 ft)
#define S_H1   12800000u     // 6.4M floats : layer-1 output (fp32)
#define S_EL   19200000u     // 0.2M
#define S_ER   19400000u     // 0.2M
#define S_OFF  19600000u     // NN+1 ints : CSR row offsets
#define S_CUR  19800000u     // NN   ints : counts -> cursors
#define S_EIDX 20000000u     // EE   ints : src id per CSR slot
#define S_DST  20800000u     // EE   ints : dst id per CSR slot
#define S_A    21600000u     // EE*4 floats : attention per slot (ends 24.8M)

// ---------------- packed f32x2 helpers (Blackwell FFMA2) ------------------------
__device__ __forceinline__ unsigned long long pk2(float lo, float hi) {
    unsigned long long r;
    asm("mov.b64 %0, {%1, %2};" : "=l"(r) : "f"(lo), "f"(hi));
    return r;
}
__device__ __forceinline__ void ffma2(unsigned long long& d,
                                      unsigned long long a, unsigned long long b) {
    asm("fma.rn.f32x2 %0, %1, %2, %0;" : "+l"(d) : "l"(a), "l"(b));
}
__device__ __forceinline__ float2 up2(unsigned long long v) {
    float2 f;
    asm("mov.b64 {%0, %1}, %2;" : "=f"(f.x), "=f"(f.y) : "l"(v));
    return f;
}

// =================================================================================
// GEMM (R7 core, measured 57.3us): ft = X @ W, fused el/er. ft stored as FP16.
// 512 threads, 128-row tile, micro-tile 8x4 per thread, packed FFMA2.
// =================================================================================
#define XPAD 132
__global__ void __launch_bounds__(512, 1)
gat_gemm_kernel(const float* __restrict__ X, const float* __restrict__ W,
                const float* __restrict__ al, const float* __restrict__ ar,
                __half* __restrict__ fth, float* __restrict__ el,
                float* __restrict__ er)
{
    extern __shared__ float smem[];
    float* Ws = smem;             // [128][128]
    float* Xs = smem + 16384;     // [128][XPAD]  Xs[k*XPAD + r]

    const int t    = threadIdx.x;
    const int lane = t & 31;
    const int warp = t >> 5;      // 0..15
    const int c0   = lane * 4;
    const int r0   = warp * 8;
    const int row0 = blockIdx.x * 128;

    {
        const float4* W4 = reinterpret_cast<const float4*>(W);
        float4* Ws4 = reinterpret_cast<float4*>(Ws);
        #pragma unroll
        for (int i = t; i < 4096; i += 512) Ws4[i] = W4[i];
    }
    const float4 alv = reinterpret_cast<const float4*>(al)[lane];
    const float4 arv = reinterpret_cast<const float4*>(ar)[lane];

    for (int i = t; i < 128 * 128; i += 512) {
        int r = i >> 7, k = i & 127;
        int row = row0 + r;
        Xs[k * XPAD + r] = (row < NN) ? X[(size_t)row * 128 + k] : 0.f;
    }
    __syncthreads();

    unsigned long long acc[4][4];
    #pragma unroll
    for (int rp = 0; rp < 4; rp++)
        #pragma unroll
        for (int c = 0; c < 4; c++) acc[rp][c] = 0ull;

    #pragma unroll 4
    for (int k = 0; k < 128; k++) {
        float4 w  = *reinterpret_cast<const float4*>(&Ws[k * 128 + c0]);
        float4 x0 = *reinterpret_cast<const float4*>(&Xs[k * XPAD + r0]);
        float4 x1 = *reinterpret_cast<const float4*>(&Xs[k * XPAD + r0 + 4]);
        unsigned long long ww[4] = {pk2(w.x, w.x), pk2(w.y, w.y),
                                    pk2(w.z, w.z), pk2(w.w, w.w)};
        unsigned long long xp[4] = {pk2(x0.x, x0.y), pk2(x0.z, x0.w),
                                    pk2(x1.x, x1.y), pk2(x1.z, x1.w)};
        #pragma unroll
        for (int rp = 0; rp < 4; rp++) {
            ffma2(acc[rp][0], xp[rp], ww[0]);
            ffma2(acc[rp][1], xp[rp], ww[1]);
            ffma2(acc[rp][2], xp[rp], ww[2]);
            ffma2(acc[rp][3], xp[rp], ww[3]);
        }
    }

    #pragma unroll
    for (int r = 0; r < 8; r++) {
        int rp = r >> 1, hl = r & 1;
        float v0 = hl ? up2(acc[rp][0]).y : up2(acc[rp][0]).x;
        float v1 = hl ? up2(acc[rp][1]).y : up2(acc[rp][1]).x;
        float v2 = hl ? up2(acc[rp][2]).y : up2(acc[rp][2]).x;
        float v3 = hl ? up2(acc[rp][3]).y : up2(acc[rp][3]).x;
        int row = row0 + r0 + r;
        float pe = v0*alv.x + v1*alv.y + v2*alv.z + v3*alv.w;
        float pr = v0*arv.x + v1*arv.y + v2*arv.z + v3*arv.w;
        pe += __shfl_down_sync(0xffffffffu, pe, 4, 8);
        pe += __shfl_down_sync(0xffffffffu, pe, 2, 8);
        pe += __shfl_down_sync(0xffffffffu, pe, 1, 8);
        pr += __shfl_down_sync(0xffffffffu, pr, 4, 8);
        pr += __shfl_down_sync(0xffffffffu, pr, 2, 8);
        pr += __shfl_down_sync(0xffffffffu, pr, 1, 8);
        if (row < NN) {
            __half2 pa = __floats2half2_rn(v0, v1);
            __half2 pb = __floats2half2_rn(v2, v3);
            uint2 pk;
            pk.x = *reinterpret_cast<unsigned int*>(&pa);
            pk.y = *reinterpret_cast<unsigned int*>(&pb);
            *reinterpret_cast<uint2*>(&fth[(size_t)row * 128 + c0]) = pk;
            if ((lane & 7) == 0) {
                int h = lane >> 3;
                el[(size_t)row * 4 + h] = pe;
                er[(size_t)row * 4 + h] = pr;
            }
        }
    }
}

// =================================================================================
// CSR build
// =================================================================================
__global__ void hist_kernel(const int* __restrict__ dst, int* __restrict__ cnt)
{
    int e = blockIdx.x * blockDim.x + threadIdx.x;
    if (e < EE) atomicAdd(&cnt[dst[e]], 1);
}

__global__ void __launch_bounds__(1024, 1)
scan_kernel(int* __restrict__ cntcur, int* __restrict__ off)
{
    __shared__ int ssum[1024];
    const int t = threadIdx.x;
    const int C = (NN + 1023) / 1024;
    int lo = t * C, hi = min(lo + C, NN);
    int s = 0;
    for (int i = lo; i < hi; i++) s += cntcur[i];
    ssum[t] = s;
    __syncthreads();
    for (int d = 1; d < 1024; d <<= 1) {
        int v = (t >= d) ? ssum[t - d] : 0;
        __syncthreads();
        ssum[t] += v;
        __syncthreads();
    }
    int run = (t > 0) ? ssum[t - 1] : 0;
    for (int i = lo; i < hi; i++) {
        int c = cntcur[i];
        off[i] = run;
        cntcur[i] = run;        // becomes scatter cursor
        run += c;
    }
    if (t == 1023) off[NN] = ssum[1023];
}

// scatter + layer-1 attention fused (el/er already computed by gemm1)
__global__ void scatter_att_kernel(const int* __restrict__ src, const int* __restrict__ dst,
                                   int* __restrict__ cur, int* __restrict__ eidx,
                                   int* __restrict__ dslot,
                                   const float* __restrict__ el,
                                   const float* __restrict__ er,
                                   float4* __restrict__ a4)
{
    int e = blockIdx.x * blockDim.x + threadIdx.x;
    if (e >= EE) return;
    int s = src[e], d = dst[e];
    int pos = atomicAdd(&cur[d], 1);
    eidx[pos]  = s;
    dslot[pos] = d;
    float4 l = *reinterpret_cast<const float4*>(&el[(size_t)s * 4]);
    float4 r = *reinterpret_cast<const float4*>(&er[(size_t)d * 4]);
    float4 v;
    float vx = l.x + r.x; vx = (vx > 0.f) ? vx : SLOPE * vx; v.x = __expf(vx);
    float vy = l.y + r.y; vy = (vy > 0.f) ? vy : SLOPE * vy; v.y = __expf(vy);
    float vz = l.z + r.z; vz = (vz > 0.f) ? vz : SLOPE * vz; v.z = __expf(vz);
    float vw = l.w + r.w; vw = (vw > 0.f) ? vw : SLOPE * vw; v.w = __expf(vw);
    a4[pos] = v;
}

// layer-2 attention (CSR slots already built)
__global__ void att_kernel(const int* __restrict__ eidx, const int* __restrict__ dslot,
                           const float* __restrict__ el, const float* __restrict__ er,
                           float4* __restrict__ a4)
{
    int t = blockIdx.x * blockDim.x + threadIdx.x;
    if (t >= EE) return;
    int s = eidx[t], d = dslot[t];
    float4 l = *reinterpret_cast<const float4*>(&el[(size_t)s * 4]);
    float4 r = *reinterpret_cast<const float4*>(&er[(size_t)d * 4]);
    float4 v;
    float vx = l.x + r.x; vx = (vx > 0.f) ? vx : SLOPE * vx; v.x = __expf(vx);
    float vy = l.y + r.y; vy = (vy > 0.f) ? vy : SLOPE * vy; v.y = __expf(vy);
    float vz = l.z + r.z; vz = (vz > 0.f) ? vz : SLOPE * vz; v.z = __expf(vz);
    float vw = l.w + r.w; vw = (vw > 0.f) ? vw : SLOPE * vw; v.w = __expf(vw);
    a4[t] = v;
}

// =================================================================================
// Gather aggregation + fused normalize + ELU. One warp per dst node.
// ft gathers are FP16 (256B/edge): lane loads 4 halves (uint2), fp32 accumulate.
// =================================================================================
__device__ __forceinline__ float elu1(float x) { return (x > 0.f) ? x : expm1f(x); }

__device__ __forceinline__ void fma_h4(float4& acc, float ah, uint2 g) {
    __half2 h01 = *reinterpret_cast<__half2*>(&g.x);
    __half2 h23 = *reinterpret_cast<__half2*>(&g.y);
    float2 f01 = __half22float2(h01);
    float2 f23 = __half22float2(h23);
    acc.x += ah * f01.x; acc.y += ah * f01.y;
    acc.z += ah * f23.x; acc.w += ah * f23.y;
}

__global__ void __launch_bounds__(256, 4)
gat_aggregate_kernel(const int* __restrict__ off, const int* __restrict__ eidx,
                     const float* __restrict__ afl, const __half* __restrict__ fth,
                     float* __restrict__ out)
{
    int d = (blockIdx.x * blockDim.x + threadIdx.x) >> 5;
    if (d >= NN) return;
    const int lane = threadIdx.x & 31;
    const int hsel = lane >> 3;            // head of this lane's 4-value chunk

    int p0 = off[d], p1 = off[d + 1];
    float4 acc = make_float4(0.f, 0.f, 0.f, 0.f);
    float den16 = 0.f;                     // lanes 0..15 partial denom, head lane&3
    const uint2* ft2 = reinterpret_cast<const uint2*>(fth);   // row = 32 uint2

    int p = p0;
    int pre = min(p1, (p0 + 3) & ~3);
    for (; p < pre; ++p) {
        int s = __ldg(&eidx[p]);
        uint2 g = __ldg(&ft2[(size_t)s * 32 + lane]);
        float a = (lane < 4) ? __ldg(&afl[(size_t)p * 4 + lane]) : 0.f;
        if (lane < 4) den16 += a;
        float ah = __shfl_sync(0xffffffffu, a, hsel);
        fma_h4(acc, ah, g);
    }
    if (p + 4 <= p1) {
        int4 s4 = __ldg(reinterpret_cast<const int4*>(&eidx[p]));
        for (; p + 4 <= p1; p += 4) {
            int4 nxt = (p + 8 <= p1)
                     ? __ldg(reinterpret_cast<const int4*>(&eidx[p + 4])) : s4;
            float a = 0.f;
            if (lane < 16) {               // lane = e*4 + h, coalesced 64B
                a = __ldg(&afl[(size_t)p * 4 + lane]);
                den16 += a;
            }
            uint2 g0 = __ldg(&ft2[(size_t)s4.x * 32 + lane]);
            uint2 g1 = __ldg(&ft2[(size_t)s4.y * 32 + lane]);
            uint2 g2 = __ldg(&ft2[(size_t)s4.z * 32 + lane]);
            uint2 g3 = __ldg(&ft2[(size_t)s4.w * 32 + lane]);
            float h0 = __shfl_sync(0xffffffffu, a, hsel);
            float h1 = __shfl_sync(0xffffffffu, a, 4 + hsel);
            float h2 = __shfl_sync(0xffffffffu, a, 8 + hsel);
            float h3 = __shfl_sync(0xffffffffu, a, 12 + hsel);
            fma_h4(acc, h0, g0);
            fma_h4(acc, h1, g1);
            fma_h4(acc, h2, g2);
            fma_h4(acc, h3, g3);
            s4 = nxt;
        }
    }
    for (; p < p1; ++p) {
        int s = __ldg(&eidx[p]);
        uint2 g = __ldg(&ft2[(size_t)s * 32 + lane]);
        float a = (lane < 4) ? __ldg(&afl[(size_t)p * 4 + lane]) : 0.f;
        if (lane < 4) den16 += a;
        float ah = __shfl_sync(0xffffffffu, a, hsel);
        fma_h4(acc, ah, g);
    }

    den16 += __shfl_down_sync(0xffffffffu, den16, 8);
    den16 += __shfl_down_sync(0xffffffffu, den16, 4);
    float inv  = 1.0f / fmaxf(den16, 1e-9f);
    float invh = __shfl_sync(0xffffffffu, inv, hsel);
    float4 r;
    r.x = elu1(acc.x * invh);
    r.y = elu1(acc.y * invh);
    r.z = elu1(acc.z * invh);
    r.w = elu1(acc.w * invh);
    reinterpret_cast<float4*>(out)[(size_t)d * 32 + lane] = r;
}

// =================================================================================
// Edge features: out[p, h*64 + 0..31] = hf[i0,h,:], [32..63] = hf[i1,h,:]
// =================================================================================
__global__ void gat_edgefeat_kernel(const float* __restrict__ hf,
                                    const int* __restrict__ ind0,
                                    const int* __restrict__ ind1,
                                    float* __restrict__ out)
{
    int idx = blockIdx.x * blockDim.x + threadIdx.x;
    if (idx >= EI * 64) return;
    int p = idx >> 6;
    int q = idx & 63;
    int h = q >> 4;
    int w = q & 15;
    int node = (w < 8) ? __ldg(&ind0[p]) : __ldg(&ind1[p]);
    float4 v = reinterpret_cast<const float4*>(hf)[(size_t)node * 32 + h * 8 + (w & 7)];
    reinterpret_cast<float4*>(out)[(size_t)p * 64 + q] = v;
}

// =================================================================================
// Launch.  Order makes launch #6 (memset=#1) the FIRST AGGREGATE so ncu -s5 -c1
// finally profiles it.
// =================================================================================
extern "C" void kernel_launch(void* const* d_in, const int* in_sizes, int n_in,
                              void* d_out, int out_size)
{
    const float* x      = (const float*)d_in[0];
    const int*   src    = (const int*)  d_in[1];
    const int*   dst    = (const int*)  d_in[2];
    const int*   indics = (const int*)  d_in[3];
    const float* W0     = (const float*)d_in[4];
    const float* al0    = (const float*)d_in[5];
    const float* ar0    = (const float*)d_in[6];
    const float* W1     = (const float*)d_in[7];
    const float* al1    = (const float*)d_in[8];
    const float* ar1    = (const float*)d_in[9];

    float* o     = (float*)d_out;
    float* h_out = o;                      // [N, 128]
    float* edges = o + (size_t)NN * 128;   // [E_IND, 256] (written LAST)

    __half* fth = (__half*)(o + S_FT);
    float* h1   = o + S_H1;
    float* el   = o + S_EL;
    float* er   = o + S_ER;
    int*   off  = (int*)(o + S_OFF);
    int*   cur  = (int*)(o + S_CUR);
    int*   eid  = (int*)(o + S_EIDX);
    int*   dsl  = (int*)(o + S_DST);
    float* afl  = o + S_A;
    float4* a4  = (float4*)afl;

    const int gemm_smem = (16384 + 128 * XPAD) * 4;    // 133,120 B
    static int attr_done = 0;
    if (!attr_done) {
        cudaFuncSetAttribute(gat_gemm_kernel,
                             cudaFuncAttributeMaxDynamicSharedMemorySize, gemm_smem);
        attr_done = 1;
    }

    const int gemm_grid = (NN + 127) / 128;            // 391
    const int edge_grid = (EE + 255) / 256;
    const int agg_grid  = (NN * 32 + 255) / 256;
    const int ef_grid   = (EI * 64 + 255) / 256;

    // #1 memset, #2 hist, #3 scan, #4 gemm1, #5 scatter+att1, #6 agg1 (ncu target)
    cudaMemsetAsync(cur, 0, NN * sizeof(int));
    hist_kernel<<<edge_grid, 256>>>(dst, cur);
    scan_kernel<<<1, 1024>>>(cur, off);

    gat_gemm_kernel<<<gemm_grid, 512, gemm_smem>>>(x, W0, al0, ar0, fth, el, er);
    scatter_att_kernel<<<edge_grid, 256>>>(src, dst, cur, eid, dsl, el, er, a4);
    gat_aggregate_kernel<<<agg_grid, 256>>>(off, eid, afl, fth, h1);

    gat_gemm_kernel<<<gemm_grid, 512, gemm_smem>>>(h1, W1, al1, ar1, fth, el, er);
    att_kernel<<<edge_grid, 256>>>(eid, dsl, el, er, a4);
    gat_aggregate_kernel<<<agg_grid, 256>>>(off, eid, afl, fth, h_out);

    gat_edgefeat_kernel<<<ef_grid, 256>>>(h_out, indics, indics + EI, edges);
}

// round 13
// speedup vs baseline: 1.0207x; 1.0001x over previous
#include <cuda_runtime.h>
#include <cuda_fp16.h>
#include <cstdint>

#define NN     50000
#define EE     800000
#define EI     200000
#define SLOPE  0.2f

// ---- scratch layout inside d_out (float offsets) -------------------------------
#define S_FT    6400000u     // NN*128 halves (fp16 ft)
#define S_H1   12800000u     // 6.4M floats : layer-1 output (fp32)
#define S_EL   19200000u
#define S_ER   19400000u
#define S_OFF  19600000u     // NN+1 ints : CSR row offsets
#define S_CUR  19800000u     // NN   ints : counts -> cursors
#define S_EIDX 20000000u     // EE   ints : src id per CSR slot
#define S_DST  20800000u     // EE   ints : dst id per CSR slot
#define S_A    21600000u     // EE*4 floats : attention per slot (ends 24.8M)

// ---------------- packed f32x2 helpers (Blackwell FFMA2) ------------------------
__device__ __forceinline__ unsigned long long pk2(float lo, float hi) {
    unsigned long long r;
    asm("mov.b64 %0, {%1, %2};" : "=l"(r) : "f"(lo), "f"(hi));
    return r;
}
__device__ __forceinline__ void ffma2(unsigned long long& d,
                                      unsigned long long a, unsigned long long b) {
    asm("fma.rn.f32x2 %0, %1, %2, %0;" : "+l"(d) : "l"(a), "l"(b));
}
__device__ __forceinline__ float2 up2(unsigned long long v) {
    float2 f;
    asm("mov.b64 {%0, %1}, %2;" : "=f"(f.x), "=f"(f.y) : "l"(v));
    return f;
}

// =================================================================================
// GEMM: ft = X @ W (fp32 math, fp16 X-tile in smem), fused el/er, fp16 ft out.
// 256 threads, tile 128 rows x 128 cols, micro-tile 8x8, 2 CTAs/SM (98KB smem,
// 128-reg budget so no spills). Also zeroes the CSR counter array when asked
// (folds the memset launch so agg1 becomes ncu's captured launch #5).
// =================================================================================
#define XPADH 136
__global__ void __launch_bounds__(256, 2)
gat_gemm_kernel(const float* __restrict__ X, const float* __restrict__ W,
                const float* __restrict__ al, const float* __restrict__ ar,
                __half* __restrict__ fth, float* __restrict__ el,
                float* __restrict__ er, int* __restrict__ zero_cur)
{
    extern __shared__ float smem[];
    float*  Ws  = smem;                           // [128][128] f32 = 64KB
    __half* Xsh = (__half*)(smem + 16384);        // [128][XPADH] half = 34.8KB

    const int t    = threadIdx.x;
    const int lane = t & 31;
    const int warp = t >> 5;                      // 0..7
    const int tr0  = warp * 16 + (lane >> 4) * 8; // 8 rows
    const int tc0  = (lane & 15) * 8;             // 8 cols
    const int row0 = blockIdx.x * 128;

    int gtid = blockIdx.x * 256 + t;              // grid*256 = 100,096 >= NN
    if (zero_cur != nullptr && gtid < NN) zero_cur[gtid] = 0;

    {
        const float4* W4 = reinterpret_cast<const float4*>(W);
        float4* Ws4 = reinterpret_cast<float4*>(Ws);
        #pragma unroll
        for (int i = t; i < 4096; i += 256) Ws4[i] = W4[i];
    }
    for (int i = t; i < 128 * 128; i += 256) {
        int r = i >> 7, k = i & 127;
        int row = row0 + r;
        Xsh[k * XPADH + r] = __float2half((row < NN) ? X[(size_t)row * 128 + k] : 0.f);
    }
    __syncthreads();

    // acc[rp][c]: row pair (2rp,2rp+1) of col tc0+c
    unsigned long long acc[4][8];
    #pragma unroll
    for (int rp = 0; rp < 4; rp++)
        #pragma unroll
        for (int c = 0; c < 8; c++) acc[rp][c] = 0ull;

    #pragma unroll 2
    for (int k = 0; k < 128; k++) {
        uint4 hx = *reinterpret_cast<const uint4*>(&Xsh[k * XPADH + tr0]); // 8 halves
        __half2 h0 = *reinterpret_cast<__half2*>(&hx.x);
        __half2 h1 = *reinterpret_cast<__half2*>(&hx.y);
        __half2 h2 = *reinterpret_cast<__half2*>(&hx.z);
        __half2 h3 = *reinterpret_cast<__half2*>(&hx.w);
        float2 f0 = __half22float2(h0);
        float2 f1 = __half22float2(h1);
        float2 f2 = __half22float2(h2);
        float2 f3 = __half22float2(h3);
        unsigned long long xp[4] = {pk2(f0.x, f0.y), pk2(f1.x, f1.y),
                                    pk2(f2.x, f2.y), pk2(f3.x, f3.y)};
        float4 wa = *reinterpret_cast<const float4*>(&Ws[k * 128 + tc0]);
        float4 wb = *reinterpret_cast<const float4*>(&Ws[k * 128 + tc0 + 4]);
        unsigned long long ww[8] = {pk2(wa.x, wa.x), pk2(wa.y, wa.y),
                                    pk2(wa.z, wa.z), pk2(wa.w, wa.w),
                                    pk2(wb.x, wb.x), pk2(wb.y, wb.y),
                                    pk2(wb.z, wb.z), pk2(wb.w, wb.w)};
        #pragma unroll
        for (int rp = 0; rp < 4; rp++)
            #pragma unroll
            for (int c = 0; c < 8; c++)
                ffma2(acc[rp][c], xp[rp], ww[c]);
    }

    float alv[8], arv[8];
    #pragma unroll
    for (int c = 0; c < 8; c++) { alv[c] = al[tc0 + c]; arv[c] = ar[tc0 + c]; }
    const int head = (lane & 15) >> 2;            // tc0 >> 5

    #pragma unroll
    for (int r = 0; r < 8; r++) {
        int rp = r >> 1, hl = r & 1;
        float v[8];
        #pragma unroll
        for (int c = 0; c < 8; c++) {
            float2 pq = up2(acc[rp][c]);
            v[c] = hl ? pq.y : pq.x;
        }
        int row = row0 + tr0 + r;
        float pe = 0.f, pr = 0.f;
        #pragma unroll
        for (int c = 0; c < 8; c++) { pe += v[c] * alv[c]; pr += v[c] * arv[c]; }
        pe += __shfl_down_sync(0xffffffffu, pe, 2, 4);
        pe += __shfl_down_sync(0xffffffffu, pe, 1, 4);
        pr += __shfl_down_sync(0xffffffffu, pr, 2, 4);
        pr += __shfl_down_sync(0xffffffffu, pr, 1, 4);
        if (row < NN) {
            __half2 pa = __floats2half2_rn(v[0], v[1]);
            __half2 pb = __floats2half2_rn(v[2], v[3]);
            __half2 pc = __floats2half2_rn(v[4], v[5]);
            __half2 pd = __floats2half2_rn(v[6], v[7]);
            uint2 w0, w1;
            w0.x = *reinterpret_cast<unsigned int*>(&pa);
            w0.y = *reinterpret_cast<unsigned int*>(&pb);
            w1.x = *reinterpret_cast<unsigned int*>(&pc);
            w1.y = *reinterpret_cast<unsigned int*>(&pd);
            *reinterpret_cast<uint2*>(&fth[(size_t)row * 128 + tc0])     = w0;
            *reinterpret_cast<uint2*>(&fth[(size_t)row * 128 + tc0 + 4]) = w1;
            if ((lane & 3) == 0) {
                el[(size_t)row * 4 + head] = pe;
                er[(size_t)row * 4 + head] = pr;
            }
        }
    }
}

// =================================================================================
// CSR build
// =================================================================================
__global__ void hist_kernel(const int* __restrict__ dst, int* __restrict__ cnt)
{
    int e = blockIdx.x * blockDim.x + threadIdx.x;
    if (e < EE) atomicAdd(&cnt[dst[e]], 1);
}

__global__ void __launch_bounds__(1024, 1)
scan_kernel(int* __restrict__ cntcur, int* __restrict__ off)
{
    __shared__ int ssum[1024];
    const int t = threadIdx.x;
    const int C = (NN + 1023) / 1024;
    int lo = t * C, hi = min(lo + C, NN);
    int s = 0;
    for (int i = lo; i < hi; i++) s += cntcur[i];
    ssum[t] = s;
    __syncthreads();
    for (int d = 1; d < 1024; d <<= 1) {
        int v = (t >= d) ? ssum[t - d] : 0;
        __syncthreads();
        ssum[t] += v;
        __syncthreads();
    }
    int run = (t > 0) ? ssum[t - 1] : 0;
    for (int i = lo; i < hi; i++) {
        int c = cntcur[i];
        off[i] = run;
        cntcur[i] = run;        // becomes scatter cursor
        run += c;
    }
    if (t == 1023) off[NN] = ssum[1023];
}

// scatter + layer-1 attention fused
__global__ void scatter_att_kernel(const int* __restrict__ src, const int* __restrict__ dst,
                                   int* __restrict__ cur, int* __restrict__ eidx,
                                   int* __restrict__ dslot,
                                   const float* __restrict__ el,
                                   const float* __restrict__ er,
                                   float4* __restrict__ a4)
{
    int e = blockIdx.x * blockDim.x + threadIdx.x;
    if (e >= EE) return;
    int s = src[e], d = dst[e];
    int pos = atomicAdd(&cur[d], 1);
    eidx[pos]  = s;
    dslot[pos] = d;
    float4 l = *reinterpret_cast<const float4*>(&el[(size_t)s * 4]);
    float4 r = *reinterpret_cast<const float4*>(&er[(size_t)d * 4]);
    float4 v;
    float vx = l.x + r.x; vx = (vx > 0.f) ? vx : SLOPE * vx; v.x = __expf(vx);
    float vy = l.y + r.y; vy = (vy > 0.f) ? vy : SLOPE * vy; v.y = __expf(vy);
    float vz = l.z + r.z; vz = (vz > 0.f) ? vz : SLOPE * vz; v.z = __expf(vz);
    float vw = l.w + r.w; vw = (vw > 0.f) ? vw : SLOPE * vw; v.w = __expf(vw);
    a4[pos] = v;
}

// layer-2 attention (CSR already built)
__global__ void att_kernel(const int* __restrict__ eidx, const int* __restrict__ dslot,
                           const float* __restrict__ el, const float* __restrict__ er,
                           float4* __restrict__ a4)
{
    int t = blockIdx.x * blockDim.x + threadIdx.x;
    if (t >= EE) return;
    int s = eidx[t], d = dslot[t];
    float4 l = *reinterpret_cast<const float4*>(&el[(size_t)s * 4]);
    float4 r = *reinterpret_cast<const float4*>(&er[(size_t)d * 4]);
    float4 v;
    float vx = l.x + r.x; vx = (vx > 0.f) ? vx : SLOPE * vx; v.x = __expf(vx);
    float vy = l.y + r.y; vy = (vy > 0.f) ? vy : SLOPE * vy; v.y = __expf(vy);
    float vz = l.z + r.z; vz = (vz > 0.f) ? vz : SLOPE * vz; v.z = __expf(vz);
    float vw = l.w + r.w; vw = (vw > 0.f) ? vw : SLOPE * vw; v.w = __expf(vw);
    a4[t] = v;
}

// =================================================================================
// Gather aggregation + fused normalize + ELU. One warp per dst node, fp16 ft rows.
// =================================================================================
__device__ __forceinline__ float elu1(float x) { return (x > 0.f) ? x : expm1f(x); }

__device__ __forceinline__ void fma_h4(float4& acc, float ah, uint2 g) {
    __half2 h01 = *reinterpret_cast<__half2*>(&g.x);
    __half2 h23 = *reinterpret_cast<__half2*>(&g.y);
    float2 f01 = __half22float2(h01);
    float2 f23 = __half22float2(h23);
    acc.x += ah * f01.x; acc.y += ah * f01.y;
    acc.z += ah * f23.x; acc.w += ah * f23.y;
}

__global__ void __launch_bounds__(256, 4)
gat_aggregate_kernel(const int* __restrict__ off, const int* __restrict__ eidx,
                     const float* __restrict__ afl, const __half* __restrict__ fth,
                     float* __restrict__ out)
{
    int d = (blockIdx.x * blockDim.x + threadIdx.x) >> 5;
    if (d >= NN) return;
    const int lane = threadIdx.x & 31;
    const int hsel = lane >> 3;

    int p0 = off[d], p1 = off[d + 1];
    float4 acc = make_float4(0.f, 0.f, 0.f, 0.f);
    float den16 = 0.f;
    const uint2* ft2 = reinterpret_cast<const uint2*>(fth);

    int p = p0;
    int pre = min(p1, (p0 + 3) & ~3);
    for (; p < pre; ++p) {
        int s = __ldg(&eidx[p]);
        uint2 g = __ldg(&ft2[(size_t)s * 32 + lane]);
        float a = (lane < 4) ? __ldg(&afl[(size_t)p * 4 + lane]) : 0.f;
        if (lane < 4) den16 += a;
        float ah = __shfl_sync(0xffffffffu, a, hsel);
        fma_h4(acc, ah, g);
    }
    if (p + 4 <= p1) {
        int4 s4 = __ldg(reinterpret_cast<const int4*>(&eidx[p]));
        for (; p + 4 <= p1; p += 4) {
            int4 nxt = (p + 8 <= p1)
                     ? __ldg(reinterpret_cast<const int4*>(&eidx[p + 4])) : s4;
            float a = 0.f;
            if (lane < 16) {
                a = __ldg(&afl[(size_t)p * 4 + lane]);
                den16 += a;
            }
            uint2 g0 = __ldg(&ft2[(size_t)s4.x * 32 + lane]);
            uint2 g1 = __ldg(&ft2[(size_t)s4.y * 32 + lane]);
            uint2 g2 = __ldg(&ft2[(size_t)s4.z * 32 + lane]);
            uint2 g3 = __ldg(&ft2[(size_t)s4.w * 32 + lane]);
            float h0 = __shfl_sync(0xffffffffu, a, hsel);
            float h1 = __shfl_sync(0xffffffffu, a, 4 + hsel);
            float h2 = __shfl_sync(0xffffffffu, a, 8 + hsel);
            float h3 = __shfl_sync(0xffffffffu, a, 12 + hsel);
            fma_h4(acc, h0, g0);
            fma_h4(acc, h1, g1);
            fma_h4(acc, h2, g2);
            fma_h4(acc, h3, g3);
            s4 = nxt;
        }
    }
    for (; p < p1; ++p) {
        int s = __ldg(&eidx[p]);
        uint2 g = __ldg(&ft2[(size_t)s * 32 + lane]);
        float a = (lane < 4) ? __ldg(&afl[(size_t)p * 4 + lane]) : 0.f;
        if (lane < 4) den16 += a;
        float ah = __shfl_sync(0xffffffffu, a, hsel);
        fma_h4(acc, ah, g);
    }

    den16 += __shfl_down_sync(0xffffffffu, den16, 8);
    den16 += __shfl_down_sync(0xffffffffu, den16, 4);
    float inv  = 1.0f / fmaxf(den16, 1e-9f);
    float invh = __shfl_sync(0xffffffffu, inv, hsel);
    float4 r;
    r.x = elu1(acc.x * invh);
    r.y = elu1(acc.y * invh);
    r.z = elu1(acc.z * invh);
    r.w = elu1(acc.w * invh);
    reinterpret_cast<float4*>(out)[(size_t)d * 32 + lane] = r;
}

// =================================================================================
// Edge features, 2 float4 per thread for ILP.
// out[p, h*64 + 0..31] = hf[i0,h,:], [32..63] = hf[i1,h,:]
// =================================================================================
__global__ void __launch_bounds__(256)
gat_edgefeat_kernel(const float* __restrict__ hf,
                    const int* __restrict__ ind0,
                    const int* __restrict__ ind1,
                    float* __restrict__ out)
{
    int idx = blockIdx.x * blockDim.x + threadIdx.x;   // EI*32 threads
    if (idx >= EI * 32) return;
    int p  = idx >> 5;
    int tq = idx & 31;
    int i0 = __ldg(&ind0[p]);
    int i1 = __ldg(&ind1[p]);
    const float4* hf4 = reinterpret_cast<const float4*>(hf);
    float4* o4 = reinterpret_cast<float4*>(out) + (size_t)p * 64;
    #pragma unroll
    for (int j = 0; j < 2; j++) {
        int q = tq * 2 + j;
        int h = q >> 4, w = q & 15;
        int node = (w < 8) ? i0 : i1;
        o4[q] = hf4[(size_t)node * 32 + h * 8 + (w & 7)];
    }
}

// =================================================================================
// Launch. gemm1 zeroes `cur` (no memset launch) so agg1 is launch #5 = ncu target.
// =================================================================================
extern "C" void kernel_launch(void* const* d_in, const int* in_sizes, int n_in,
                              void* d_out, int out_size)
{
    const float* x      = (const float*)d_in[0];
    const int*   src    = (const int*)  d_in[1];
    const int*   dst    = (const int*)  d_in[2];
    const int*   indics = (const int*)  d_in[3];
    const float* W0     = (const float*)d_in[4];
    const float* al0    = (const float*)d_in[5];
    const float* ar0    = (const float*)d_in[6];
    const float* W1     = (const float*)d_in[7];
    const float* al1    = (const float*)d_in[8];
    const float* ar1    = (const float*)d_in[9];

    float* o     = (float*)d_out;
    float* h_out = o;                      // [N, 128]
    float* edges = o + (size_t)NN * 128;   // [E_IND, 256] (written LAST)

    __half* fth = (__half*)(o + S_FT);
    float* h1   = o + S_H1;
    float* el   = o + S_EL;
    float* er   = o + S_ER;
    int*   off  = (int*)(o + S_OFF);
    int*   cur  = (int*)(o + S_CUR);
    int*   eid  = (int*)(o + S_EIDX);
    int*   dsl  = (int*)(o + S_DST);
    float* afl  = o + S_A;
    float4* a4  = (float4*)afl;

    const int gemm_smem = 16384 * 4 + 128 * XPADH * 2;   // 100,352 B
    static int attr_done = 0;
    if (!attr_done) {
        cudaFuncSetAttribute(gat_gemm_kernel,
                             cudaFuncAttributeMaxDynamicSharedMemorySize, gemm_smem);
        attr_done = 1;
    }

    const int gemm_grid = (NN + 127) / 128;            // 391
    const int edge_grid = (EE + 255) / 256;
    const int agg_grid  = (NN * 32 + 255) / 256;
    const int ef_grid   = (EI * 32 + 255) / 256;       // 25000

    // #1 gemm1 (also zeroes cur), #2 hist, #3 scan, #4 scatter+att1,
    // #5 agg1  <-- ncu -s5 -c1 capture target
    gat_gemm_kernel<<<gemm_grid, 256, gemm_smem>>>(x, W0, al0, ar0, fth, el, er, cur);
    hist_kernel<<<edge_grid, 256>>>(dst, cur);
    scan_kernel<<<1, 1024>>>(cur, off);
    scatter_att_kernel<<<edge_grid, 256>>>(src, dst, cur, eid, dsl, el, er, a4);
    gat_aggregate_kernel<<<agg_grid, 256>>>(off, eid, afl, fth, h1);

    gat_gemm_kernel<<<gemm_grid, 256, gemm_smem>>>(h1, W1, al1, ar1, fth, el, er, nullptr);
    att_kernel<<<edge_grid, 256>>>(eid, dsl, el, er, a4);
    gat_aggregate_kernel<<<agg_grid, 256>>>(off, eid, afl, fth, h_out);

    gat_edgefeat_kernel<<<ef_grid, 256>>>(h_out, indics, indics + EI, edges);
}

// round 16
// speedup vs baseline: 1.1730x; 1.1492x over previous
#include <cuda_runtime.h>
#include <cuda_fp16.h>
#include <cstdint>

#define NN     50000
#define EE     800000
#define EI     200000
#define SLOPE  0.2f

// ---- scratch layout inside d_out (float offsets) -------------------------------
#define S_FT    6400000u     // NN*128 halves (fp16 ft)
#define S_H1   12800000u     // 6.4M floats : layer-1 output (fp32)
#define S_EL   19200000u
#define S_ER   19400000u
#define S_OFF  19600000u     // NN+1 ints : CSR row offsets
#define S_CUR  19800000u     // NN   ints : counts -> cursors
#define S_EIDX 20000000u     // EE   ints : src id per CSR slot
#define S_DST  20800000u     // EE   ints : dst id per CSR slot
#define S_A    21600000u     // EE*4 floats : attention per slot (ends 24.8M)

__device__ __forceinline__ uint32_t smem_u32(const void* p) {
    uint32_t a;
    asm("{ .reg .u64 t; cvta.to.shared.u64 t, %1; cvt.u32.u64 %0, t; }"
        : "=r"(a) : "l"(p));
    return a;
}

#define LDSM_X4(r0, r1, r2, r3, addr)                                        \
    asm volatile("ldmatrix.sync.aligned.m8n8.x4.shared.b16 {%0,%1,%2,%3},[%4];" \
                 : "=r"(r0), "=r"(r1), "=r"(r2), "=r"(r3) : "r"(addr))

#define LDSM_X4_T(r0, r1, r2, r3, addr)                                      \
    asm volatile("ldmatrix.sync.aligned.m8n8.x4.trans.shared.b16 {%0,%1,%2,%3},[%4];" \
                 : "=r"(r0), "=r"(r1), "=r"(r2), "=r"(r3) : "r"(addr))

#define MMA16816(c0, c1, c2, c3, a0, a1, a2, a3, b0, b1)                     \
    asm volatile("mma.sync.aligned.m16n8k16.row.col.f32.f16.f16.f32 "        \
                 "{%0,%1,%2,%3},{%4,%5,%6,%7},{%8,%9},{%0,%1,%2,%3};"        \
                 : "+f"(c0), "+f"(c1), "+f"(c2), "+f"(c3)                    \
                 : "r"(a0), "r"(a1), "r"(a2), "r"(a3), "r"(b0), "r"(b1))

// =================================================================================
// Tensor-core GEMM: ft = X @ W (fp16 in, fp32 acc), fused per-head el/er,
// fp16 ft out. 256 threads = 8 warps; CTA tile 128x128; warp tile m16 x n128;
// K=128 in 8 chunks. gemm1 also does the CSR histogram (folds a launch so the
// aggregate lands in ncu's capture slot = 4th kernel launch).
// =================================================================================
#define XPH 136                               // padded halves per row (272B stride)
__global__ void __launch_bounds__(256, 2)
gat_gemm_tc(const float* __restrict__ X, const float* __restrict__ W,
            const float* __restrict__ al, const float* __restrict__ ar,
            __half* __restrict__ fth, float* __restrict__ el,
            float* __restrict__ er,
            const int* __restrict__ histdst, int* __restrict__ cnt)
{
    extern __shared__ __half sm[];
    __half* Xh = sm;                          // [128][XPH]
    __half* Wh = sm + 128 * XPH;              // [128][XPH]
    float*  als = (float*)(sm + 2 * 128 * XPH);        // [128]
    float*  ars = als + 128;                           // [128]

    const int t    = threadIdx.x;
    const int lane = t & 31;
    const int warp = t >> 5;                  // 0..7
    const int rw   = warp * 16;
    const int row0 = blockIdx.x * 128;

    // fused histogram (layer-1 call only)
    if (histdst != nullptr) {
        int gtid = blockIdx.x * 256 + t;      // grid*256 = 100096
        #pragma unroll
        for (int i = 0; i < 8; i++) {
            int e = gtid + i * 100096;
            if (e < EE) atomicAdd(&cnt[histdst[e]], 1);
        }
    }

    // stage al/ar
    if (t < 128) { als[t] = al[t]; ars[t] = ar[t]; }

    // load W -> fp16 smem
    {
        const float4* W4 = reinterpret_cast<const float4*>(W);
        for (int i = t; i < 128 * 32; i += 256) {
            float4 v = W4[i];
            int r = i >> 5, c = (i & 31) * 4;
            __half2 p0 = __floats2half2_rn(v.x, v.y);
            __half2 p1 = __floats2half2_rn(v.z, v.w);
            *reinterpret_cast<__half2*>(&Wh[r * XPH + c])     = p0;
            *reinterpret_cast<__half2*>(&Wh[r * XPH + c + 2]) = p1;
        }
    }
    // load X tile -> fp16 smem (zero-pad rows >= NN)
    {
        const float4* X4 = reinterpret_cast<const float4*>(X);
        for (int i = t; i < 128 * 32; i += 256) {
            int r = i >> 5, c = (i & 31) * 4;
            int row = row0 + r;
            float4 v = (row < NN) ? X4[(size_t)row * 32 + (i & 31)]
                                  : make_float4(0.f, 0.f, 0.f, 0.f);
            __half2 p0 = __floats2half2_rn(v.x, v.y);
            __half2 p1 = __floats2half2_rn(v.z, v.w);
            *reinterpret_cast<__half2*>(&Xh[r * XPH + c])     = p0;
            *reinterpret_cast<__half2*>(&Xh[r * XPH + c + 2]) = p1;
        }
    }
    __syncthreads();

    // acc[j][0..3]: n-tile j (cols 8j..8j+7); rows (rw+lane/4, +8),
    // cols 8j+2*(lane&3)+{0,1}
    float acc[16][4];
    #pragma unroll
    for (int j = 0; j < 16; j++)
        #pragma unroll
        for (int c = 0; c < 4; c++) acc[j][c] = 0.f;

    const uint32_t aBase = smem_u32(Xh) +
        (((rw + (lane & 15)) * XPH) + (lane >> 4) * 8) * 2;
    const uint32_t bBase = smem_u32(Wh) +
        (((lane & 15) * XPH) + (lane >> 4) * 8) * 2;

    #pragma unroll 2
    for (int kb = 0; kb < 8; kb++) {
        uint32_t a0, a1, a2, a3;
        LDSM_X4(a0, a1, a2, a3, aBase + kb * 16 * 2);
        #pragma unroll
        for (int j2 = 0; j2 < 8; j2++) {
            uint32_t b0, b1, b2, b3;
            LDSM_X4_T(b0, b1, b2, b3, bBase + (kb * 16 * XPH + j2 * 16) * 2);
            MMA16816(acc[2*j2][0],   acc[2*j2][1],   acc[2*j2][2],   acc[2*j2][3],
                     a0, a1, a2, a3, b0, b1);
            MMA16816(acc[2*j2+1][0], acc[2*j2+1][1], acc[2*j2+1][2], acc[2*j2+1][3],
                     a0, a1, a2, a3, b2, b3);
        }
    }

    // ---- el/er: per-head dot (head h = tiles 4h..4h+3), reduce over 4 lanes ----
    const int q = lane & 3;
    float pe0[4], pr0[4], pe1[4], pr1[4];
    #pragma unroll
    for (int h = 0; h < 4; h++) { pe0[h]=pr0[h]=pe1[h]=pr1[h]=0.f; }
    #pragma unroll
    for (int j = 0; j < 16; j++) {
        int c = 8 * j + 2 * q, h = j >> 2;
        float a0l = als[c], a1l = als[c + 1];
        float a0r = ars[c], a1r = ars[c + 1];
        pe0[h] += acc[j][0] * a0l + acc[j][1] * a1l;
        pr0[h] += acc[j][0] * a0r + acc[j][1] * a1r;
        pe1[h] += acc[j][2] * a0l + acc[j][3] * a1l;
        pr1[h] += acc[j][2] * a0r + acc[j][3] * a1r;
    }
    #pragma unroll
    for (int h = 0; h < 4; h++) {
        pe0[h] += __shfl_xor_sync(0xffffffffu, pe0[h], 1);
        pe0[h] += __shfl_xor_sync(0xffffffffu, pe0[h], 2);
        pr0[h] += __shfl_xor_sync(0xffffffffu, pr0[h], 1);
        pr0[h] += __shfl_xor_sync(0xffffffffu, pr0[h], 2);
        pe1[h] += __shfl_xor_sync(0xffffffffu, pe1[h], 1);
        pe1[h] += __shfl_xor_sync(0xffffffffu, pe1[h], 2);
        pr1[h] += __shfl_xor_sync(0xffffffffu, pr1[h], 1);
        pr1[h] += __shfl_xor_sync(0xffffffffu, pr1[h], 2);
    }
    int r0g = row0 + rw + (lane >> 2);
    int r1g = r0g + 8;
    if (q == 0) {
        if (r0g < NN) {
            *reinterpret_cast<float4*>(&el[(size_t)r0g * 4]) =
                make_float4(pe0[0], pe0[1], pe0[2], pe0[3]);
            *reinterpret_cast<float4*>(&er[(size_t)r0g * 4]) =
                make_float4(pr0[0], pr0[1], pr0[2], pr0[3]);
        }
        if (r1g < NN) {
            *reinterpret_cast<float4*>(&el[(size_t)r1g * 4]) =
                make_float4(pe1[0], pe1[1], pe1[2], pe1[3]);
            *reinterpret_cast<float4*>(&er[(size_t)r1g * 4]) =
                make_float4(pr1[0], pr1[1], pr1[2], pr1[3]);
        }
    }

    // ---- ft: stage fp16 in smem (reuse Xh), then coalesced store ----
    __syncthreads();
    {
        int rs0 = rw + (lane >> 2);
        #pragma unroll
        for (int j = 0; j < 16; j++) {
            int c = 8 * j + 2 * q;
            *reinterpret_cast<__half2*>(&Xh[rs0 * XPH + c]) =
                __floats2half2_rn(acc[j][0], acc[j][1]);
            *reinterpret_cast<__half2*>(&Xh[(rs0 + 8) * XPH + c]) =
                __floats2half2_rn(acc[j][2], acc[j][3]);
        }
    }
    __syncthreads();
    // uint4 = 8 halves: 16 segs x 8 halves = full 128-col row (R14 bug was uint2).
    for (int i = t; i < 128 * 16; i += 256) {
        int r = i >> 4, seg = i & 15;
        int row = row0 + r;
        if (row < NN) {
            uint4 v = *reinterpret_cast<const uint4*>(&Xh[r * XPH + seg * 8]);
            *reinterpret_cast<uint4*>(&fth[(size_t)row * 128 + seg * 8]) = v;
        }
    }
}

// =================================================================================
// CSR scan (single block) — counts -> offsets + cursors
// =================================================================================
__global__ void __launch_bounds__(1024, 1)
scan_kernel(int* __restrict__ cntcur, int* __restrict__ off)
{
    __shared__ int ssum[1024];
    const int t = threadIdx.x;
    const int C = (NN + 1023) / 1024;
    int lo = t * C, hi = min(lo + C, NN);
    int s = 0;
    for (int i = lo; i < hi; i++) s += cntcur[i];
    ssum[t] = s;
    __syncthreads();
    for (int d = 1; d < 1024; d <<= 1) {
        int v = (t >= d) ? ssum[t - d] : 0;
        __syncthreads();
        ssum[t] += v;
        __syncthreads();
    }
    int run = (t > 0) ? ssum[t - 1] : 0;
    for (int i = lo; i < hi; i++) {
        int c = cntcur[i];
        off[i] = run;
        cntcur[i] = run;
        run += c;
    }
    if (t == 1023) off[NN] = ssum[1023];
}

// scatter + layer-1 attention fused
__global__ void scatter_att_kernel(const int* __restrict__ src, const int* __restrict__ dst,
                                   int* __restrict__ cur, int* __restrict__ eidx,
                                   int* __restrict__ dslot,
                                   const float* __restrict__ el,
                                   const float* __restrict__ er,
                                   float4* __restrict__ a4)
{
    int e = blockIdx.x * blockDim.x + threadIdx.x;
    if (e >= EE) return;
    int s = src[e], d = dst[e];
    int pos = atomicAdd(&cur[d], 1);
    eidx[pos]  = s;
    dslot[pos] = d;
    float4 l = *reinterpret_cast<const float4*>(&el[(size_t)s * 4]);
    float4 r = *reinterpret_cast<const float4*>(&er[(size_t)d * 4]);
    float4 v;
    float vx = l.x + r.x; vx = (vx > 0.f) ? vx : SLOPE * vx; v.x = __expf(vx);
    float vy = l.y + r.y; vy = (vy > 0.f) ? vy : SLOPE * vy; v.y = __expf(vy);
    float vz = l.z + r.z; vz = (vz > 0.f) ? vz : SLOPE * vz; v.z = __expf(vz);
    float vw = l.w + r.w; vw = (vw > 0.f) ? vw : SLOPE * vw; v.w = __expf(vw);
    a4[pos] = v;
}

// layer-2 attention (CSR already built)
__global__ void att_kernel(const int* __restrict__ eidx, const int* __restrict__ dslot,
                           const float* __restrict__ el, const float* __restrict__ er,
                           float4* __restrict__ a4)
{
    int t = blockIdx.x * blockDim.x + threadIdx.x;
    if (t >= EE) return;
    int s = eidx[t], d = dslot[t];
    float4 l = *reinterpret_cast<const float4*>(&el[(size_t)s * 4]);
    float4 r = *reinterpret_cast<const float4*>(&er[(size_t)d * 4]);
    float4 v;
    float vx = l.x + r.x; vx = (vx > 0.f) ? vx : SLOPE * vx; v.x = __expf(vx);
    float vy = l.y + r.y; vy = (vy > 0.f) ? vy : SLOPE * vy; v.y = __expf(vy);
    float vz = l.z + r.z; vz = (vz > 0.f) ? vz : SLOPE * vz; v.z = __expf(vz);
    float vw = l.w + r.w; vw = (vw > 0.f) ? vw : SLOPE * vw; v.w = __expf(vw);
    a4[t] = v;
}

// =================================================================================
// Gather aggregation + fused normalize + ELU. One warp per dst node, fp16 ft rows.
// =================================================================================
__device__ __forceinline__ float elu1(float x) { return (x > 0.f) ? x : expm1f(x); }

__device__ __forceinline__ void fma_h4(float4& acc, float ah, uint2 g) {
    __half2 h01 = *reinterpret_cast<__half2*>(&g.x);
    __half2 h23 = *reinterpret_cast<__half2*>(&g.y);
    float2 f01 = __half22float2(h01);
    float2 f23 = __half22float2(h23);
    acc.x += ah * f01.x; acc.y += ah * f01.y;
    acc.z += ah * f23.x; acc.w += ah * f23.y;
}

__global__ void __launch_bounds__(256, 4)
gat_aggregate_kernel(const int* __restrict__ off, const int* __restrict__ eidx,
                     const float* __restrict__ afl, const __half* __restrict__ fth,
                     float* __restrict__ out)
{
    int d = (blockIdx.x * blockDim.x + threadIdx.x) >> 5;
    if (d >= NN) return;
    const int lane = threadIdx.x & 31;
    const int hsel = lane >> 3;

    int p0 = off[d], p1 = off[d + 1];
    float4 acc = make_float4(0.f, 0.f, 0.f, 0.f);
    float den16 = 0.f;
    const uint2* ft2 = reinterpret_cast<const uint2*>(fth);

    int p = p0;
    int pre = min(p1, (p0 + 3) & ~3);
    for (; p < pre; ++p) {
        int s = __ldg(&eidx[p]);
        uint2 g = __ldg(&ft2[(size_t)s * 32 + lane]);
        float a = (lane < 4) ? __ldg(&afl[(size_t)p * 4 + lane]) : 0.f;
        if (lane < 4) den16 += a;
        float ah = __shfl_sync(0xffffffffu, a, hsel);
        fma_h4(acc, ah, g);
    }
    if (p + 4 <= p1) {
        int4 s4 = __ldg(reinterpret_cast<const int4*>(&eidx[p]));
        for (; p + 4 <= p1; p += 4) {
            int4 nxt = (p + 8 <= p1)
                     ? __ldg(reinterpret_cast<const int4*>(&eidx[p + 4])) : s4;
            float a = 0.f;
            if (lane < 16) {
                a = __ldg(&afl[(size_t)p * 4 + lane]);
                den16 += a;
            }
            uint2 g0 = __ldg(&ft2[(size_t)s4.x * 32 + lane]);
            uint2 g1 = __ldg(&ft2[(size_t)s4.y * 32 + lane]);
            uint2 g2 = __ldg(&ft2[(size_t)s4.z * 32 + lane]);
            uint2 g3 = __ldg(&ft2[(size_t)s4.w * 32 + lane]);
            float h0 = __shfl_sync(0xffffffffu, a, hsel);
            float h1 = __shfl_sync(0xffffffffu, a, 4 + hsel);
            float h2 = __shfl_sync(0xffffffffu, a, 8 + hsel);
            float h3 = __shfl_sync(0xffffffffu, a, 12 + hsel);
            fma_h4(acc, h0, g0);
            fma_h4(acc, h1, g1);
            fma_h4(acc, h2, g2);
            fma_h4(acc, h3, g3);
            s4 = nxt;
        }
    }
    for (; p < p1; ++p) {
        int s = __ldg(&eidx[p]);
        uint2 g = __ldg(&ft2[(size_t)s * 32 + lane]);
        float a = (lane < 4) ? __ldg(&afl[(size_t)p * 4 + lane]) : 0.f;
        if (lane < 4) den16 += a;
        float ah = __shfl_sync(0xffffffffu, a, hsel);
        fma_h4(acc, ah, g);
    }

    den16 += __shfl_down_sync(0xffffffffu, den16, 8);
    den16 += __shfl_down_sync(0xffffffffu, den16, 4);
    float inv  = 1.0f / fmaxf(den16, 1e-9f);
    float invh = __shfl_sync(0xffffffffu, inv, hsel);
    float4 r;
    r.x = elu1(acc.x * invh);
    r.y = elu1(acc.y * invh);
    r.z = elu1(acc.z * invh);
    r.w = elu1(acc.w * invh);
    reinterpret_cast<float4*>(out)[(size_t)d * 32 + lane] = r;
}

// =================================================================================
// Edge features, 2 float4 per thread.
// =================================================================================
__global__ void __launch_bounds__(256)
gat_edgefeat_kernel(const float* __restrict__ hf,
                    const int* __restrict__ ind0,
                    const int* __restrict__ ind1,
                    float* __restrict__ out)
{
    int idx = blockIdx.x * blockDim.x + threadIdx.x;
    if (idx >= EI * 32) return;
    int p  = idx >> 5;
    int tq = idx & 31;
    int i0 = __ldg(&ind0[p]);
    int i1 = __ldg(&ind1[p]);
    const float4* hf4 = reinterpret_cast<const float4*>(hf);
    float4* o4 = reinterpret_cast<float4*>(out) + (size_t)p * 64;
    #pragma unroll
    for (int j = 0; j < 2; j++) {
        int q = tq * 2 + j;
        int h = q >> 4, w = q & 15;
        int node = (w < 8) ? i0 : i1;
        o4[q] = hf4[(size_t)node * 32 + h * 8 + (w & 7)];
    }
}

// =================================================================================
// Launch.  k1 gemm1(+hist), k2 scan, k3 scatter+att1, k4 agg1 (ncu capture slot).
// =================================================================================
extern "C" void kernel_launch(void* const* d_in, const int* in_sizes, int n_in,
                              void* d_out, int out_size)
{
    const float* x      = (const float*)d_in[0];
    const int*   src    = (const int*)  d_in[1];
    const int*   dst    = (const int*)  d_in[2];
    const int*   indics = (const int*)  d_in[3];
    const float* W0     = (const float*)d_in[4];
    const float* al0    = (const float*)d_in[5];
    const float* ar0    = (const float*)d_in[6];
    const float* W1     = (const float*)d_in[7];
    const float* al1    = (const float*)d_in[8];
    const float* ar1    = (const float*)d_in[9];

    float* o     = (float*)d_out;
    float* h_out = o;
    float* edges = o + (size_t)NN * 128;

    __half* fth = (__half*)(o + S_FT);
    float* h1   = o + S_H1;
    float* el   = o + S_EL;
    float* er   = o + S_ER;
    int*   off  = (int*)(o + S_OFF);
    int*   cur  = (int*)(o + S_CUR);
    int*   eid  = (int*)(o + S_EIDX);
    int*   dsl  = (int*)(o + S_DST);
    float* afl  = o + S_A;
    float4* a4  = (float4*)afl;

    const int gemm_smem = 2 * 128 * XPH * 2 + 2 * 128 * 4;   // 70,656 B
    static int attr_done = 0;
    if (!attr_done) {
        cudaFuncSetAttribute(gat_gemm_tc,
                             cudaFuncAttributeMaxDynamicSharedMemorySize, gemm_smem);
        attr_done = 1;
    }

    const int gemm_grid = (NN + 127) / 128;            // 391
    const int edge_grid = (EE + 255) / 256;
    const int agg_grid  = (NN * 32 + 255) / 256;
    const int ef_grid   = (EI * 32 + 255) / 256;

    cudaMemsetAsync(cur, 0, NN * sizeof(int));         // memset node (not a kernel)

    gat_gemm_tc<<<gemm_grid, 256, gemm_smem>>>(x, W0, al0, ar0, fth, el, er, dst, cur);
    scan_kernel<<<1, 1024>>>(cur, off);
    scatter_att_kernel<<<edge_grid, 256>>>(src, dst, cur, eid, dsl, el, er, a4);
    gat_aggregate_kernel<<<agg_grid, 256>>>(off, eid, afl, fth, h1);   // k4 = ncu

    gat_gemm_tc<<<gemm_grid, 256, gemm_smem>>>(h1, W1, al1, ar1, fth, el, er,
                                               nullptr, nullptr);
    att_kernel<<<edge_grid, 256>>>(eid, dsl, el, er, a4);
    gat_aggregate_kernel<<<agg_grid, 256>>>(off, eid, afl, fth, h_out);

    gat_edgefeat_kernel<<<ef_grid, 256>>>(h_out, indics, indics + EI, edges);
}